// round 2
// baseline (speedup 1.0000x reference)
#include <cuda_runtime.h>
#include <math.h>

#define NATOMS 20000
#define NEDGES 200000
#define CDIM 64
#define KDIM 20
#define RCUT 5.0f
#define NORMF 10.0f
#define EPSF 1e-12f
#define PI_F 3.14159265358979f

// scratch: per (atom, channel) 16 slots: [0]=way0, [1..3]=way1, [4..12]=way2
__device__ float g_scr[(size_t)NATOMS * CDIM * 16];
__device__ int g_active[NEDGES];
__device__ int g_count;

__global__ void k_zero() {
    size_t idx = (size_t)blockIdx.x * blockDim.x + threadIdx.x;
    const size_t n4 = (size_t)NATOMS * CDIM * 16 / 4;
    if (idx < n4) reinterpret_cast<float4*>(g_scr)[idx] = make_float4(0.f, 0.f, 0.f, 0.f);
    if (idx == 0) g_count = 0;
}

__global__ void k_compact(const int* __restrict__ eidx, const float* __restrict__ coord) {
    int e = blockIdx.x * blockDim.x + threadIdx.x;
    if (e >= NEDGES) return;
    int i = eidx[e];
    int j = eidx[NEDGES + e];
    float dx = coord[3 * j + 0] - coord[3 * i + 0];
    float dy = coord[3 * j + 1] - coord[3 * i + 1];
    float dz = coord[3 * j + 2] - coord[3 * i + 2];
    float d2 = dx * dx + dy * dy + dz * dz + EPSF;
    // fc == 0 exactly (fp32) for d >= RCUT -> all messages are exactly zero; skip.
    if (d2 < RCUT * RCUT) {
        int p = atomicAdd(&g_count, 1);
        g_active[p] = e;
    }
}

// COMBOS fn index map:
// 0:(0,0,0) 1:(0,1,1) 2:(0,2,2) 3:(1,0,1) 4:(1,1,0) 5:(1,1,2)
// 6:(1,2,1) 7:(2,0,2) 8:(2,1,1) 9:(2,2,0) 10:(2,2,2)
__global__ void k_edge(const int* __restrict__ eidx, const float* __restrict__ coord,
                       const float* __restrict__ t0, const float* __restrict__ t1,
                       const float* __restrict__ t2, const float* __restrict__ rbf_w) {
    __shared__ float rbf_sh[4][KDIM];
    const int tid = threadIdx.x;
    const int c = tid & 63;
    const int es = tid >> 6;
    const int count = g_count;

    for (int base = blockIdx.x * 4; base < count; base += gridDim.x * 4) {
        int ae = base + es;
        bool act = ae < count;
        int i = 0, j = 0;
        float ux = 0.f, uy = 0.f, uz = 0.f;
        if (act) {
            int e = g_active[ae];
            i = eidx[e];
            j = eidx[NEDGES + e];
            float dx = coord[3 * j + 0] - coord[3 * i + 0];
            float dy = coord[3 * j + 1] - coord[3 * i + 1];
            float dz = coord[3 * j + 2] - coord[3 * i + 2];
            float d2 = dx * dx + dy * dy + dz * dz + EPSF;
            float d = sqrtf(d2);
            float inv = 1.0f / d;
            ux = dx * inv; uy = dy * inv; uz = dz * inv;
            if (c < KDIM) {
                float x = fminf(d * (1.0f / RCUT), 1.0f);
                float fc = 0.5f * (cosf(PI_F * x) + 1.0f);
                float pref = sqrtf(2.0f / RCUT);
                rbf_sh[es][c] = pref * sinf((float)(c + 1) * PI_F * d * (1.0f / RCUT)) * inv * fc;
            }
        }
        __syncthreads();
        if (act) {
            float rbf[KDIM];
#pragma unroll
            for (int k = 0; k < KDIM; k++) rbf[k] = rbf_sh[es][k];

            float fn[11];
            for (int m = 0; m < 11; m++) {
                const float* w = rbf_w + (size_t)m * KDIM * CDIM + c;
                float acc = 0.f;
#pragma unroll
                for (int k = 0; k < KDIM; k++) acc += rbf[k] * __ldg(w + k * CDIM);
                fn[m] = acc;
            }

            size_t bj = (size_t)j * CDIM + c;
            float s0 = __ldg(t0 + bj);
            float va[3];
            va[0] = __ldg(t1 + bj * 3 + 0);
            va[1] = __ldg(t1 + bj * 3 + 1);
            va[2] = __ldg(t1 + bj * 3 + 2);
            float M[9];
#pragma unroll
            for (int m9 = 0; m9 < 9; m9++) M[m9] = __ldg(t2 + bj * 9 + m9);

            float u[3] = {ux, uy, uz};
            float d1 = va[0] * ux + va[1] * uy + va[2] * uz;
            float w3[3];
#pragma unroll
            for (int a = 0; a < 3; a++)
                w3[a] = M[a * 3 + 0] * ux + M[a * 3 + 1] * uy + M[a * 3 + 2] * uz;
            float q2 = w3[0] * ux + w3[1] * uy + w3[2] * uz;

            const float sc = 1.0f / NORMF;
            float o0 = (fn[0] * s0 + fn[4] * d1 + fn[9] * q2) * sc;
            float c1 = fn[1] * s0 + fn[6] * d1;
            float o1[3];
#pragma unroll
            for (int p = 0; p < 3; p++)
                o1[p] = (c1 * u[p] + fn[3] * va[p] + fn[8] * w3[p]) * sc;
            float o2[9];
#pragma unroll
            for (int a = 0; a < 3; a++) {
                float ga = fn[2] * s0 * u[a] + fn[5] * va[a] + fn[10] * w3[a];
#pragma unroll
                for (int b = 0; b < 3; b++)
                    o2[a * 3 + b] = (ga * u[b] + fn[7] * M[a * 3 + b]) * sc;
            }

            float* dst = g_scr + ((size_t)i * CDIM + c) * 16;
            atomicAdd(dst + 0, o0);
#pragma unroll
            for (int p = 0; p < 3; p++) atomicAdd(dst + 1 + p, o1[p]);
#pragma unroll
            for (int m9 = 0; m9 < 9; m9++) atomicAdd(dst + 4 + m9, o2[m9]);
        }
        __syncthreads();
    }
}

__device__ __forceinline__ float sigf(float x) { return 1.0f / (1.0f + __expf(-x)); }

// 4 atoms per block, 64 threads per atom (one per output channel)
__global__ void k_si(const float* __restrict__ t0, const float* __restrict__ t1,
                     const float* __restrict__ t2,
                     const float* __restrict__ w0, const float* __restrict__ b0,
                     const float* __restrict__ w1, const float* __restrict__ w2,
                     const float* __restrict__ actw, float* __restrict__ out) {
    extern __shared__ float ws[];               // [3][64][64] = 48KB dynamic (opt-in)
    __shared__ float aggS[4][CDIM][16];         // 16KB static
    __shared__ float b0s[CDIM], aws[3][CDIM];

    int tid = threadIdx.x;
    for (int idx = tid; idx < 3 * CDIM * CDIM; idx += 256) {
        int which = idx >> 12;
        int r = idx & 4095;
        const float* src = (which == 0) ? w0 : ((which == 1) ? w1 : w2);
        ws[idx] = src[r];
    }
    if (tid < CDIM) {
        b0s[tid] = b0[tid];
        aws[0][tid] = actw[tid];
        aws[1][tid] = actw[CDIM + tid];
        aws[2][tid] = actw[2 * CDIM + tid];
    }

    int a = tid >> 6, c = tid & 63;
    int n = blockIdx.x * 4 + a;
    size_t bn = (size_t)n * CDIM + c;
    const float* scp = g_scr + bn * 16;
    aggS[a][c][0] = t0[bn] + scp[0];
#pragma unroll
    for (int p = 0; p < 3; p++) aggS[a][c][1 + p] = t1[bn * 3 + p] + scp[1 + p];
#pragma unroll
    for (int m = 0; m < 9; m++) aggS[a][c][4 + m] = t2[bn * 9 + m] + scp[4 + m];
    aggS[a][c][13] = 0.f; aggS[a][c][14] = 0.f; aggS[a][c][15] = 0.f;
    __syncthreads();

    int o = c;
    const float* W0 = ws;
    const float* W1 = ws + CDIM * CDIM;
    const float* W2 = ws + 2 * CDIM * CDIM;
    float y0 = b0s[o];
    float y1[3] = {0.f, 0.f, 0.f};
    float y2[9] = {0.f, 0.f, 0.f, 0.f, 0.f, 0.f, 0.f, 0.f, 0.f};
#pragma unroll 4
    for (int cc = 0; cc < CDIM; cc++) {
        float4 A0 = *reinterpret_cast<const float4*>(&aggS[a][cc][0]);
        float4 A1 = *reinterpret_cast<const float4*>(&aggS[a][cc][4]);
        float4 A2 = *reinterpret_cast<const float4*>(&aggS[a][cc][8]);
        float A12 = aggS[a][cc][12];
        float wv0 = W0[cc * CDIM + o];
        float wv1 = W1[cc * CDIM + o];
        float wv2 = W2[cc * CDIM + o];
        y0 += A0.x * wv0;
        y1[0] += A0.y * wv1; y1[1] += A0.z * wv1; y1[2] += A0.w * wv1;
        y2[0] += A1.x * wv2; y2[1] += A1.y * wv2; y2[2] += A1.z * wv2; y2[3] += A1.w * wv2;
        y2[4] += A2.x * wv2; y2[5] += A2.y * wv2; y2[6] += A2.z * wv2; y2[7] += A2.w * wv2;
        y2[8] += A12 * wv2;
    }

    float z0 = y0 * sigf(aws[0][o] * y0);
    float r1 = y1[0] * y1[0] + y1[1] * y1[1] + y1[2] * y1[2];
    float g1 = sigf(aws[1][o] * sqrtf(r1 + EPSF));
    float r2 = 0.f;
#pragma unroll
    for (int m = 0; m < 9; m++) r2 += y2[m] * y2[m];
    float g2 = sigf(aws[2][o] * sqrtf(r2 + EPSF));

    size_t bo = (size_t)n * CDIM + o;
    out[bo] = z0 + aggS[a][o][0];
    float* out1 = out + (size_t)NATOMS * CDIM;
#pragma unroll
    for (int p = 0; p < 3; p++) out1[bo * 3 + p] = y1[p] * g1 + aggS[a][o][1 + p];
    float* out2 = out + (size_t)NATOMS * CDIM * 4;
#pragma unroll
    for (int m = 0; m < 9; m++) out2[bo * 9 + m] = y2[m] * g2 + aggS[a][o][4 + m];
}

extern "C" void kernel_launch(void* const* d_in, const int* in_sizes, int n_in,
                              void* d_out, int out_size) {
    const float* t0    = (const float*)d_in[0];
    const float* t1    = (const float*)d_in[1];
    const float* t2    = (const float*)d_in[2];
    const float* coord = (const float*)d_in[3];
    const int*   eidx  = (const int*)d_in[4];
    const float* rbf_w = (const float*)d_in[5];
    const float* w0    = (const float*)d_in[6];
    const float* b0    = (const float*)d_in[7];
    const float* w1    = (const float*)d_in[8];
    const float* w2    = (const float*)d_in[9];
    const float* aw    = (const float*)d_in[10];
    float* out = (float*)d_out;

    // Opt in to >48KB combined smem for k_si (48KB dynamic + ~17.4KB static).
    // Non-stream API: executes immediately, not captured, deterministic.
    cudaFuncSetAttribute(k_si, cudaFuncAttributeMaxDynamicSharedMemorySize,
                         3 * CDIM * CDIM * (int)sizeof(float));

    k_zero<<<(NATOMS * CDIM * 16 / 4 + 255) / 256, 256>>>();
    k_compact<<<(NEDGES + 255) / 256, 256>>>(eidx, coord);
    k_edge<<<888, 256>>>(eidx, coord, t0, t1, t2, rbf_w);
    k_si<<<NATOMS / 4, 256, 3 * CDIM * CDIM * sizeof(float)>>>(t0, t1, t2, w0, b0, w1, w2, aw, out);
}

// round 3
// speedup vs baseline: 1.5910x; 1.5910x over previous
#include <cuda_runtime.h>
#include <math.h>

#define NATOMS 20000
#define NEDGES 200000
#define CDIM 64
#define KDIM 20
#define RCUT 5.0f
#define NORMF 10.0f
#define EPSF 1e-12f
#define PI_F 3.14159265358979f
#define NC (NATOMS * CDIM)

// SoA scratch planes: [13][NATOMS*CDIM]; plane 0 = way0, 1..3 = way1, 4..12 = way2.
// Initialized with the input features (residual start), edges atomically accumulate.
__device__ float g_scr[(size_t)13 * NC];
__device__ int g_active[NEDGES];
__device__ int g_count;

__global__ void k_init(const float* __restrict__ t0, const float* __restrict__ t1,
                       const float* __restrict__ t2) {
    int idx = blockIdx.x * blockDim.x + threadIdx.x;
    if (idx >= NC) return;
    if (idx == 0) g_count = 0;
    g_scr[idx] = t0[idx];
#pragma unroll
    for (int p = 0; p < 3; p++)
        g_scr[(size_t)(1 + p) * NC + idx] = t1[(size_t)idx * 3 + p];
#pragma unroll
    for (int m = 0; m < 9; m++)
        g_scr[(size_t)(4 + m) * NC + idx] = t2[(size_t)idx * 9 + m];
}

__global__ void k_compact(const int* __restrict__ eidx, const float* __restrict__ coord) {
    int e = blockIdx.x * blockDim.x + threadIdx.x;
    if (e >= NEDGES) return;
    int i = eidx[e];
    int j = eidx[NEDGES + e];
    float dx = coord[3 * j + 0] - coord[3 * i + 0];
    float dy = coord[3 * j + 1] - coord[3 * i + 1];
    float dz = coord[3 * j + 2] - coord[3 * i + 2];
    float d2 = dx * dx + dy * dy + dz * dz + EPSF;
    // fc == 0 exactly (fp32) for d >= RCUT -> message contributions are exactly zero.
    if (d2 < RCUT * RCUT) {
        int p = atomicAdd(&g_count, 1);
        g_active[p] = e;
    }
}

// COMBOS fn index map:
// 0:(0,0,0) 1:(0,1,1) 2:(0,2,2) 3:(1,0,1) 4:(1,1,0) 5:(1,1,2)
// 6:(1,2,1) 7:(2,0,2) 8:(2,1,1) 9:(2,2,0) 10:(2,2,2)
__global__ void k_edge(const int* __restrict__ eidx, const float* __restrict__ coord,
                       const float* __restrict__ t0, const float* __restrict__ t1,
                       const float* __restrict__ t2, const float* __restrict__ rbf_w) {
    __shared__ float rbf_sh[4][KDIM];
    const int tid = threadIdx.x;
    const int c = tid & 63;
    const int es = tid >> 6;
    const int count = g_count;

    for (int base = blockIdx.x * 4; base < count; base += gridDim.x * 4) {
        int ae = base + es;
        bool act = ae < count;
        int i = 0, j = 0;
        float ux = 0.f, uy = 0.f, uz = 0.f;
        if (act) {
            int e = g_active[ae];
            i = eidx[e];
            j = eidx[NEDGES + e];
            float dx = coord[3 * j + 0] - coord[3 * i + 0];
            float dy = coord[3 * j + 1] - coord[3 * i + 1];
            float dz = coord[3 * j + 2] - coord[3 * i + 2];
            float d2 = dx * dx + dy * dy + dz * dz + EPSF;
            float d = sqrtf(d2);
            float inv = 1.0f / d;
            ux = dx * inv; uy = dy * inv; uz = dz * inv;
            if (c < KDIM) {
                float x = fminf(d * (1.0f / RCUT), 1.0f);
                float fc = 0.5f * (cosf(PI_F * x) + 1.0f);
                float pref = sqrtf(2.0f / RCUT);
                rbf_sh[es][c] = pref * sinf((float)(c + 1) * PI_F * d * (1.0f / RCUT)) * inv * fc;
            }
        }
        __syncthreads();
        if (act) {
            float rbf[KDIM];
#pragma unroll
            for (int k = 0; k < KDIM; k++) rbf[k] = rbf_sh[es][k];

            float fn[11];
            for (int m = 0; m < 11; m++) {
                const float* w = rbf_w + (size_t)m * KDIM * CDIM + c;
                float acc = 0.f;
#pragma unroll
                for (int k = 0; k < KDIM; k++) acc += rbf[k] * __ldg(w + k * CDIM);
                fn[m] = acc;
            }

            size_t bj = (size_t)j * CDIM + c;
            float s0 = __ldg(t0 + bj);
            float va[3];
            va[0] = __ldg(t1 + bj * 3 + 0);
            va[1] = __ldg(t1 + bj * 3 + 1);
            va[2] = __ldg(t1 + bj * 3 + 2);
            float M[9];
#pragma unroll
            for (int m9 = 0; m9 < 9; m9++) M[m9] = __ldg(t2 + bj * 9 + m9);

            float u[3] = {ux, uy, uz};
            float d1 = va[0] * ux + va[1] * uy + va[2] * uz;
            float w3[3];
#pragma unroll
            for (int a = 0; a < 3; a++)
                w3[a] = M[a * 3 + 0] * ux + M[a * 3 + 1] * uy + M[a * 3 + 2] * uz;
            float q2 = w3[0] * ux + w3[1] * uy + w3[2] * uz;

            const float sc = 1.0f / NORMF;
            float o0 = (fn[0] * s0 + fn[4] * d1 + fn[9] * q2) * sc;
            float c1 = fn[1] * s0 + fn[6] * d1;
            float o1[3];
#pragma unroll
            for (int p = 0; p < 3; p++)
                o1[p] = (c1 * u[p] + fn[3] * va[p] + fn[8] * w3[p]) * sc;
            float o2[9];
#pragma unroll
            for (int a = 0; a < 3; a++) {
                float ga = fn[2] * s0 * u[a] + fn[5] * va[a] + fn[10] * w3[a];
#pragma unroll
                for (int b = 0; b < 3; b++)
                    o2[a * 3 + b] = (ga * u[b] + fn[7] * M[a * 3 + b]) * sc;
            }

            size_t bi = (size_t)i * CDIM + c;
            atomicAdd(&g_scr[bi], o0);
#pragma unroll
            for (int p = 0; p < 3; p++) atomicAdd(&g_scr[(size_t)(1 + p) * NC + bi], o1[p]);
#pragma unroll
            for (int m9 = 0; m9 < 9; m9++) atomicAdd(&g_scr[(size_t)(4 + m9) * NC + bi], o2[m9]);
        }
        __syncthreads();
    }
}

__device__ __forceinline__ float sigf(float x) { return 1.0f / (1.0f + __expf(-x)); }

// Persistent, weight-stationary. 8 atoms per tile, 2 atoms per thread.
// Threads: stage phase (a8 = tid>>5, lanes cover channels); compute phase
// (pair p = tid>>6, out channel o = tid&63; atoms 2p, 2p+1).
__global__ void __launch_bounds__(256, 2)
k_si(const float* __restrict__ w0, const float* __restrict__ b0,
     const float* __restrict__ w1, const float* __restrict__ w2,
     const float* __restrict__ actw, float* __restrict__ out) {
    extern __shared__ float ws[];                 // [3][64][64] = 48KB dynamic
    __shared__ float aggS[8][CDIM][16];           // 32KB
    __shared__ float b0s[CDIM], aws[3][CDIM];

    const int tid = threadIdx.x;
    for (int idx = tid; idx < 3 * CDIM * CDIM; idx += 256) {
        int which = idx >> 12;
        int r = idx & 4095;
        const float* src = (which == 0) ? w0 : ((which == 1) ? w1 : w2);
        ws[idx] = src[r];
    }
    if (tid < CDIM) {
        b0s[tid] = b0[tid];
        aws[0][tid] = actw[tid];
        aws[1][tid] = actw[CDIM + tid];
        aws[2][tid] = actw[2 * CDIM + tid];
    }

    const int a8 = tid >> 5, c2 = tid & 31;
    const int p = tid >> 6, o = tid & 63;
    const int a0 = 2 * p, a1 = 2 * p + 1;
    const float* W0 = ws;
    const float* W1 = ws + CDIM * CDIM;
    const float* W2 = ws + 2 * CDIM * CDIM;

    for (int tile = blockIdx.x; tile < NATOMS / 8; tile += gridDim.x) {
        const int nbase = tile * 8;
        // ---- stage 8 atoms x 64 ch x 13 slots from SoA planes (coalesced) ----
        {
            size_t base = (size_t)(nbase + a8) * CDIM;
#pragma unroll
            for (int half = 0; half < 2; half++) {
                int cc = c2 + half * 32;
#pragma unroll
                for (int s = 0; s < 13; s++)
                    aggS[a8][cc][s] = g_scr[(size_t)s * NC + base + cc];
            }
        }
        __syncthreads();

        // ---- compute: 2 atoms per thread, 26 accumulator chains ----
        float y0A = b0s[o], y0B = b0s[o];
        float y1A[3] = {0.f, 0.f, 0.f}, y1B[3] = {0.f, 0.f, 0.f};
        float y2A[9] = {0.f}, y2B[9] = {0.f};
#pragma unroll 4
        for (int cc = 0; cc < CDIM; cc++) {
            float wv0 = W0[cc * CDIM + o];
            float wv1 = W1[cc * CDIM + o];
            float wv2 = W2[cc * CDIM + o];
            const float* A = &aggS[a0][cc][0];
            const float* B = &aggS[a1][cc][0];
            float4 A0 = *reinterpret_cast<const float4*>(A);
            float4 A1 = *reinterpret_cast<const float4*>(A + 4);
            float4 A2 = *reinterpret_cast<const float4*>(A + 8);
            float A12 = A[12];
            float4 Bv0 = *reinterpret_cast<const float4*>(B);
            float4 Bv1 = *reinterpret_cast<const float4*>(B + 4);
            float4 Bv2 = *reinterpret_cast<const float4*>(B + 8);
            float B12 = B[12];

            y0A += A0.x * wv0;
            y1A[0] += A0.y * wv1; y1A[1] += A0.z * wv1; y1A[2] += A0.w * wv1;
            y2A[0] += A1.x * wv2; y2A[1] += A1.y * wv2; y2A[2] += A1.z * wv2; y2A[3] += A1.w * wv2;
            y2A[4] += A2.x * wv2; y2A[5] += A2.y * wv2; y2A[6] += A2.z * wv2; y2A[7] += A2.w * wv2;
            y2A[8] += A12 * wv2;

            y0B += Bv0.x * wv0;
            y1B[0] += Bv0.y * wv1; y1B[1] += Bv0.z * wv1; y1B[2] += Bv0.w * wv1;
            y2B[0] += Bv1.x * wv2; y2B[1] += Bv1.y * wv2; y2B[2] += Bv1.z * wv2; y2B[3] += Bv1.w * wv2;
            y2B[4] += Bv2.x * wv2; y2B[5] += Bv2.y * wv2; y2B[6] += Bv2.z * wv2; y2B[7] += Bv2.w * wv2;
            y2B[8] += B12 * wv2;
        }

        // ---- activations + residual + store, both atoms ----
        float* out1 = out + (size_t)NATOMS * CDIM;
        float* out2 = out + (size_t)NATOMS * CDIM * 4;
        {
            size_t bo = (size_t)(nbase + a0) * CDIM + o;
            float z0 = y0A * sigf(aws[0][o] * y0A);
            float r1 = y1A[0] * y1A[0] + y1A[1] * y1A[1] + y1A[2] * y1A[2];
            float g1 = sigf(aws[1][o] * sqrtf(r1 + EPSF));
            float r2 = 0.f;
#pragma unroll
            for (int m = 0; m < 9; m++) r2 += y2A[m] * y2A[m];
            float g2 = sigf(aws[2][o] * sqrtf(r2 + EPSF));
            out[bo] = z0 + aggS[a0][o][0];
#pragma unroll
            for (int q = 0; q < 3; q++) out1[bo * 3 + q] = y1A[q] * g1 + aggS[a0][o][1 + q];
#pragma unroll
            for (int m = 0; m < 9; m++) out2[bo * 9 + m] = y2A[m] * g2 + aggS[a0][o][4 + m];
        }
        {
            size_t bo = (size_t)(nbase + a1) * CDIM + o;
            float z0 = y0B * sigf(aws[0][o] * y0B);
            float r1 = y1B[0] * y1B[0] + y1B[1] * y1B[1] + y1B[2] * y1B[2];
            float g1 = sigf(aws[1][o] * sqrtf(r1 + EPSF));
            float r2 = 0.f;
#pragma unroll
            for (int m = 0; m < 9; m++) r2 += y2B[m] * y2B[m];
            float g2 = sigf(aws[2][o] * sqrtf(r2 + EPSF));
            out[bo] = z0 + aggS[a1][o][0];
#pragma unroll
            for (int q = 0; q < 3; q++) out1[bo * 3 + q] = y1B[q] * g1 + aggS[a1][o][1 + q];
#pragma unroll
            for (int m = 0; m < 9; m++) out2[bo * 9 + m] = y2B[m] * g2 + aggS[a1][o][4 + m];
        }
        __syncthreads();   // aggS reused next tile
    }
}

extern "C" void kernel_launch(void* const* d_in, const int* in_sizes, int n_in,
                              void* d_out, int out_size) {
    const float* t0    = (const float*)d_in[0];
    const float* t1    = (const float*)d_in[1];
    const float* t2    = (const float*)d_in[2];
    const float* coord = (const float*)d_in[3];
    const int*   eidx  = (const int*)d_in[4];
    const float* rbf_w = (const float*)d_in[5];
    const float* w0    = (const float*)d_in[6];
    const float* b0    = (const float*)d_in[7];
    const float* w1    = (const float*)d_in[8];
    const float* w2    = (const float*)d_in[9];
    const float* aw    = (const float*)d_in[10];
    float* out = (float*)d_out;

    // Opt in to 48KB dynamic smem (combined with 33.8KB static).
    cudaFuncSetAttribute(k_si, cudaFuncAttributeMaxDynamicSharedMemorySize,
                         3 * CDIM * CDIM * (int)sizeof(float));

    k_init<<<(NC + 255) / 256, 256>>>(t0, t1, t2);
    k_compact<<<(NEDGES + 255) / 256, 256>>>(eidx, coord);
    k_edge<<<888, 256>>>(eidx, coord, t0, t1, t2, rbf_w);
    k_si<<<296, 256, 3 * CDIM * CDIM * sizeof(float)>>>(w0, b0, w1, w2, aw, out);
}

// round 4
// speedup vs baseline: 1.8468x; 1.1608x over previous
#include <cuda_runtime.h>
#include <math.h>

#define NATOMS 20000
#define NEDGES 200000
#define CDIM 64
#define KDIM 20
#define RCUT 5.0f
#define NORMF 10.0f
#define EPSF 1e-12f
#define PI_F 3.14159265358979f
#define NC (NATOMS * CDIM)

#define TATOMS 16          // atoms per k_si tile
#define ASTRIDE 836        // padded per-atom smem stride (13*64=832 +4 -> bank shift 4)

// SoA scratch planes: [13][NATOMS*CDIM]; plane 0 = way0, 1..3 = way1, 4..12 = way2.
// Initialized with the input features (residual start), edges atomically accumulate.
__device__ float g_scr[(size_t)13 * NC];
__device__ int g_active[NEDGES];
__device__ int g_count;

__global__ void k_init(const float* __restrict__ t0, const float* __restrict__ t1,
                       const float* __restrict__ t2) {
    int idx = blockIdx.x * blockDim.x + threadIdx.x;
    if (idx >= NC) return;
    if (idx == 0) g_count = 0;
    g_scr[idx] = t0[idx];
#pragma unroll
    for (int p = 0; p < 3; p++)
        g_scr[(size_t)(1 + p) * NC + idx] = t1[(size_t)idx * 3 + p];
#pragma unroll
    for (int m = 0; m < 9; m++)
        g_scr[(size_t)(4 + m) * NC + idx] = t2[(size_t)idx * 9 + m];
}

__global__ void k_compact(const int* __restrict__ eidx, const float* __restrict__ coord) {
    int e = blockIdx.x * blockDim.x + threadIdx.x;
    if (e >= NEDGES) return;
    int i = eidx[e];
    int j = eidx[NEDGES + e];
    float dx = coord[3 * j + 0] - coord[3 * i + 0];
    float dy = coord[3 * j + 1] - coord[3 * i + 1];
    float dz = coord[3 * j + 2] - coord[3 * i + 2];
    float d2 = dx * dx + dy * dy + dz * dz + EPSF;
    // fc == 0 exactly (fp32) for d >= RCUT -> message contributions are exactly zero.
    if (d2 < RCUT * RCUT) {
        int p = atomicAdd(&g_count, 1);
        g_active[p] = e;
    }
}

// COMBOS fn index map:
// 0:(0,0,0) 1:(0,1,1) 2:(0,2,2) 3:(1,0,1) 4:(1,1,0) 5:(1,1,2)
// 6:(1,2,1) 7:(2,0,2) 8:(2,1,1) 9:(2,2,0) 10:(2,2,2)
__global__ void k_edge(const int* __restrict__ eidx, const float* __restrict__ coord,
                       const float* __restrict__ t0, const float* __restrict__ t1,
                       const float* __restrict__ t2, const float* __restrict__ rbf_w) {
    __shared__ float rbf_sh[4][KDIM];
    const int tid = threadIdx.x;
    const int c = tid & 63;
    const int es = tid >> 6;
    const int count = g_count;

    for (int base = blockIdx.x * 4; base < count; base += gridDim.x * 4) {
        int ae = base + es;
        bool act = ae < count;
        int i = 0, j = 0;
        float ux = 0.f, uy = 0.f, uz = 0.f;
        if (act) {
            int e = g_active[ae];
            i = eidx[e];
            j = eidx[NEDGES + e];
            float dx = coord[3 * j + 0] - coord[3 * i + 0];
            float dy = coord[3 * j + 1] - coord[3 * i + 1];
            float dz = coord[3 * j + 2] - coord[3 * i + 2];
            float d2 = dx * dx + dy * dy + dz * dz + EPSF;
            float d = sqrtf(d2);
            float inv = 1.0f / d;
            ux = dx * inv; uy = dy * inv; uz = dz * inv;
            if (c < KDIM) {
                float x = fminf(d * (1.0f / RCUT), 1.0f);
                float fc = 0.5f * (cosf(PI_F * x) + 1.0f);
                float pref = sqrtf(2.0f / RCUT);
                rbf_sh[es][c] = pref * sinf((float)(c + 1) * PI_F * d * (1.0f / RCUT)) * inv * fc;
            }
        }
        __syncthreads();
        if (act) {
            float rbf[KDIM];
#pragma unroll
            for (int k = 0; k < KDIM; k++) rbf[k] = rbf_sh[es][k];

            float fn[11];
            for (int m = 0; m < 11; m++) {
                const float* w = rbf_w + (size_t)m * KDIM * CDIM + c;
                float acc = 0.f;
#pragma unroll
                for (int k = 0; k < KDIM; k++) acc += rbf[k] * __ldg(w + k * CDIM);
                fn[m] = acc;
            }

            size_t bj = (size_t)j * CDIM + c;
            float s0 = __ldg(t0 + bj);
            float va[3];
            va[0] = __ldg(t1 + bj * 3 + 0);
            va[1] = __ldg(t1 + bj * 3 + 1);
            va[2] = __ldg(t1 + bj * 3 + 2);
            float M[9];
#pragma unroll
            for (int m9 = 0; m9 < 9; m9++) M[m9] = __ldg(t2 + bj * 9 + m9);

            float u[3] = {ux, uy, uz};
            float d1 = va[0] * ux + va[1] * uy + va[2] * uz;
            float w3[3];
#pragma unroll
            for (int a = 0; a < 3; a++)
                w3[a] = M[a * 3 + 0] * ux + M[a * 3 + 1] * uy + M[a * 3 + 2] * uz;
            float q2 = w3[0] * ux + w3[1] * uy + w3[2] * uz;

            const float sc = 1.0f / NORMF;
            float o0 = (fn[0] * s0 + fn[4] * d1 + fn[9] * q2) * sc;
            float c1 = fn[1] * s0 + fn[6] * d1;
            float o1[3];
#pragma unroll
            for (int p = 0; p < 3; p++)
                o1[p] = (c1 * u[p] + fn[3] * va[p] + fn[8] * w3[p]) * sc;
            float o2[9];
#pragma unroll
            for (int a = 0; a < 3; a++) {
                float ga = fn[2] * s0 * u[a] + fn[5] * va[a] + fn[10] * w3[a];
#pragma unroll
                for (int b = 0; b < 3; b++)
                    o2[a * 3 + b] = (ga * u[b] + fn[7] * M[a * 3 + b]) * sc;
            }

            size_t bi = (size_t)i * CDIM + c;
            atomicAdd(&g_scr[bi], o0);
#pragma unroll
            for (int p = 0; p < 3; p++) atomicAdd(&g_scr[(size_t)(1 + p) * NC + bi], o1[p]);
#pragma unroll
            for (int m9 = 0; m9 < 9; m9++) atomicAdd(&g_scr[(size_t)(4 + m9) * NC + bi], o2[m9]);
        }
        __syncthreads();
    }
}

__device__ __forceinline__ float sigf(float x) { return 1.0f / (1.0f + __expf(-x)); }

// Persistent, weight-stationary. TATOMS=16 atoms per tile.
// Each thread: 1 atom (a = tid>>4), 4 output channels (o4 = (tid&15)*4).
// Inner loop over cc: 13 scalar agg LDS (broadcast across the 16 threads of
// the same atom) + 3 float4 weight LDS feed 52 FMAs -> FFMA-bound.
__global__ void __launch_bounds__(256, 2)
k_si(const float* __restrict__ w0, const float* __restrict__ b0,
     const float* __restrict__ w1, const float* __restrict__ w2,
     const float* __restrict__ actw, float* __restrict__ out) {
    extern __shared__ float ws[];                       // [3][64][64] = 48KB dynamic
    __shared__ float aggS[TATOMS * ASTRIDE];            // 16 * 836 * 4 = 53504 B
    __shared__ float b0s[CDIM], aws[3][CDIM];

    const int tid = threadIdx.x;
    for (int idx = tid; idx < 3 * CDIM * CDIM; idx += 256) {
        int which = idx >> 12;
        int r = idx & 4095;
        const float* src = (which == 0) ? w0 : ((which == 1) ? w1 : w2);
        ws[idx] = src[r];
    }
    if (tid < CDIM) {
        b0s[tid] = b0[tid];
        aws[0][tid] = actw[tid];
        aws[1][tid] = actw[CDIM + tid];
        aws[2][tid] = actw[2 * CDIM + tid];
    }

    const int a = tid >> 4;            // atom within tile
    const int o4 = (tid & 15) * 4;     // first of 4 output channels
    const int sa = tid >> 6;           // staging: 4 atoms per pass
    const int sc_ = tid & 63;          // staging: channel
    const float* W0 = ws;
    const float* W1 = ws + CDIM * CDIM;
    const float* W2 = ws + 2 * CDIM * CDIM;
    float* out1 = out + (size_t)NATOMS * CDIM;
    float* out2 = out + (size_t)NATOMS * CDIM * 4;

    for (int tile = blockIdx.x; tile < NATOMS / TATOMS; tile += gridDim.x) {
        const int nbase = tile * TATOMS;
        // ---- stage 16 atoms x 13 slots x 64 ch from SoA planes (coalesced) ----
#pragma unroll
        for (int pass = 0; pass < 4; pass++) {
            int aa = sa + pass * 4;
            size_t gb = (size_t)(nbase + aa) * CDIM + sc_;
#pragma unroll
            for (int s = 0; s < 13; s++)
                aggS[aa * ASTRIDE + s * 64 + sc_] = g_scr[(size_t)s * NC + gb];
        }
        __syncthreads();

        // ---- compute: 4 output channels x 13 slots = 52 accumulators ----
        float y0[4], y1[3][4], y2[9][4];
#pragma unroll
        for (int q = 0; q < 4; q++) y0[q] = b0s[o4 + q];
#pragma unroll
        for (int s = 0; s < 3; s++)
#pragma unroll
            for (int q = 0; q < 4; q++) y1[s][q] = 0.f;
#pragma unroll
        for (int s = 0; s < 9; s++)
#pragma unroll
            for (int q = 0; q < 4; q++) y2[s][q] = 0.f;

        const float* ag = &aggS[a * ASTRIDE];
#pragma unroll 2
        for (int cc = 0; cc < CDIM; cc++) {
            float4 wv0 = *reinterpret_cast<const float4*>(&W0[cc * CDIM + o4]);
            float4 wv1 = *reinterpret_cast<const float4*>(&W1[cc * CDIM + o4]);
            float4 wv2 = *reinterpret_cast<const float4*>(&W2[cc * CDIM + o4]);
            float v0 = ag[cc];
            y0[0] += v0 * wv0.x; y0[1] += v0 * wv0.y; y0[2] += v0 * wv0.z; y0[3] += v0 * wv0.w;
#pragma unroll
            for (int s = 0; s < 3; s++) {
                float v = ag[(1 + s) * 64 + cc];
                y1[s][0] += v * wv1.x; y1[s][1] += v * wv1.y;
                y1[s][2] += v * wv1.z; y1[s][3] += v * wv1.w;
            }
#pragma unroll
            for (int s = 0; s < 9; s++) {
                float v = ag[(4 + s) * 64 + cc];
                y2[s][0] += v * wv2.x; y2[s][1] += v * wv2.y;
                y2[s][2] += v * wv2.z; y2[s][3] += v * wv2.w;
            }
        }

        // ---- activations + residual; contiguous float4 stores ----
        const int n = nbase + a;
        float r0v[4], r1v[12], r2v[36];
#pragma unroll
        for (int q = 0; q < 4; q++) {
            int o = o4 + q;
            float z0 = y0[q] * sigf(aws[0][o] * y0[q]);
            float n1 = y1[0][q] * y1[0][q] + y1[1][q] * y1[1][q] + y1[2][q] * y1[2][q];
            float g1 = sigf(aws[1][o] * sqrtf(n1 + EPSF));
            float n2 = 0.f;
#pragma unroll
            for (int s = 0; s < 9; s++) n2 += y2[s][q] * y2[s][q];
            float g2 = sigf(aws[2][o] * sqrtf(n2 + EPSF));
            r0v[q] = z0 + ag[o];
#pragma unroll
            for (int s = 0; s < 3; s++) r1v[q * 3 + s] = y1[s][q] * g1 + ag[(1 + s) * 64 + o];
#pragma unroll
            for (int s = 0; s < 9; s++) r2v[q * 9 + s] = y2[s][q] * g2 + ag[(4 + s) * 64 + o];
        }
        {
            size_t b = (size_t)n * CDIM + o4;
            *reinterpret_cast<float4*>(&out[b]) = make_float4(r0v[0], r0v[1], r0v[2], r0v[3]);
            float* p1 = out1 + b * 3;
#pragma unroll
            for (int v = 0; v < 3; v++)
                *reinterpret_cast<float4*>(&p1[v * 4]) =
                    make_float4(r1v[v * 4 + 0], r1v[v * 4 + 1], r1v[v * 4 + 2], r1v[v * 4 + 3]);
            float* p2 = out2 + b * 9;
#pragma unroll
            for (int v = 0; v < 9; v++)
                *reinterpret_cast<float4*>(&p2[v * 4]) =
                    make_float4(r2v[v * 4 + 0], r2v[v * 4 + 1], r2v[v * 4 + 2], r2v[v * 4 + 3]);
        }
        __syncthreads();   // aggS reused next tile
    }
}

extern "C" void kernel_launch(void* const* d_in, const int* in_sizes, int n_in,
                              void* d_out, int out_size) {
    const float* t0    = (const float*)d_in[0];
    const float* t1    = (const float*)d_in[1];
    const float* t2    = (const float*)d_in[2];
    const float* coord = (const float*)d_in[3];
    const int*   eidx  = (const int*)d_in[4];
    const float* rbf_w = (const float*)d_in[5];
    const float* w0    = (const float*)d_in[6];
    const float* b0    = (const float*)d_in[7];
    const float* w1    = (const float*)d_in[8];
    const float* w2    = (const float*)d_in[9];
    const float* aw    = (const float*)d_in[10];
    float* out = (float*)d_out;

    // Opt in to 48KB dynamic smem (combined with ~54KB static).
    cudaFuncSetAttribute(k_si, cudaFuncAttributeMaxDynamicSharedMemorySize,
                         3 * CDIM * CDIM * (int)sizeof(float));

    k_init<<<(NC + 255) / 256, 256>>>(t0, t1, t2);
    k_compact<<<(NEDGES + 255) / 256, 256>>>(eidx, coord);
    k_edge<<<888, 256>>>(eidx, coord, t0, t1, t2, rbf_w);
    k_si<<<296, 256, 3 * CDIM * CDIM * sizeof(float)>>>(w0, b0, w1, w2, aw, out);
}

// round 5
// speedup vs baseline: 2.0868x; 1.1299x over previous
#include <cuda_runtime.h>
#include <math.h>

#define NATOMS 20000
#define NEDGES 200000
#define CDIM 64
#define KDIM 20
#define RCUT 5.0f
#define NORMF 10.0f
#define EPSF 1e-12f
#define PI_F 3.14159265358979f
#define NC (NATOMS * CDIM)

#define TATOMS 16          // atoms per k_si tile
#define ASTRIDE 836        // per-atom smem stride in floats (13*64=832 +4; 836%32=4, 16B aligned)

// Scratch planes [13][NC] hold ONLY edge sums, zeroed lazily for touched atoms.
__device__ float g_scr[(size_t)13 * NC];
__device__ int g_active[NEDGES];
__device__ int g_flag[NATOMS];
__device__ int g_touched[NATOMS];
__device__ int g_count;
__device__ int g_ntouched;

__global__ void k_reset() {
    int idx = blockIdx.x * blockDim.x + threadIdx.x;
    if (idx < NATOMS) g_flag[idx] = 0;
    if (idx == 0) { g_count = 0; g_ntouched = 0; }
}

__global__ void k_compact(const int* __restrict__ eidx, const float* __restrict__ coord) {
    int e = blockIdx.x * blockDim.x + threadIdx.x;
    if (e >= NEDGES) return;
    int i = eidx[e];
    int j = eidx[NEDGES + e];
    float dx = coord[3 * j + 0] - coord[3 * i + 0];
    float dy = coord[3 * j + 1] - coord[3 * i + 1];
    float dz = coord[3 * j + 2] - coord[3 * i + 2];
    float d2 = dx * dx + dy * dy + dz * dz + EPSF;
    // fc == 0 exactly (fp32) for d >= RCUT -> message contributions are exactly zero.
    if (d2 < RCUT * RCUT) {
        int p = atomicAdd(&g_count, 1);
        g_active[p] = e;
        if (atomicOr(&g_flag[i], 1) == 0) {
            int q = atomicAdd(&g_ntouched, 1);
            g_touched[q] = i;
        }
    }
}

// Zero the 13 scratch planes for touched atoms only (~19% of atoms).
__global__ void k_zero_touched() {
    const int nt = g_ntouched;
    for (int t = blockIdx.x; t < nt; t += gridDim.x) {
        size_t b = (size_t)g_touched[t] * CDIM + threadIdx.x;   // 64 threads
#pragma unroll
        for (int s = 0; s < 13; s++) g_scr[(size_t)s * NC + b] = 0.f;
    }
}

// COMBOS fn index map:
// 0:(0,0,0) 1:(0,1,1) 2:(0,2,2) 3:(1,0,1) 4:(1,1,0) 5:(1,1,2)
// 6:(1,2,1) 7:(2,0,2) 8:(2,1,1) 9:(2,2,0) 10:(2,2,2)
__global__ void k_edge(const int* __restrict__ eidx, const float* __restrict__ coord,
                       const float* __restrict__ t0, const float* __restrict__ t1,
                       const float* __restrict__ t2, const float* __restrict__ rbf_w) {
    __shared__ float rbf_sh[4][KDIM];
    const int tid = threadIdx.x;
    const int c = tid & 63;
    const int es = tid >> 6;
    const int count = g_count;

    for (int base = blockIdx.x * 4; base < count; base += gridDim.x * 4) {
        int ae = base + es;
        bool act = ae < count;
        int i = 0, j = 0;
        float ux = 0.f, uy = 0.f, uz = 0.f;
        if (act) {
            int e = g_active[ae];
            i = eidx[e];
            j = eidx[NEDGES + e];
            float dx = coord[3 * j + 0] - coord[3 * i + 0];
            float dy = coord[3 * j + 1] - coord[3 * i + 1];
            float dz = coord[3 * j + 2] - coord[3 * i + 2];
            float d2 = dx * dx + dy * dy + dz * dz + EPSF;
            float d = sqrtf(d2);
            float inv = 1.0f / d;
            ux = dx * inv; uy = dy * inv; uz = dz * inv;
            if (c < KDIM) {
                float x = fminf(d * (1.0f / RCUT), 1.0f);
                float fc = 0.5f * (cosf(PI_F * x) + 1.0f);
                float pref = sqrtf(2.0f / RCUT);
                rbf_sh[es][c] = pref * sinf((float)(c + 1) * PI_F * d * (1.0f / RCUT)) * inv * fc;
            }
        }
        __syncthreads();
        if (act) {
            float rbf[KDIM];
#pragma unroll
            for (int k = 0; k < KDIM; k++) rbf[k] = rbf_sh[es][k];

            float fn[11];
            for (int m = 0; m < 11; m++) {
                const float* w = rbf_w + (size_t)m * KDIM * CDIM + c;
                float acc = 0.f;
#pragma unroll
                for (int k = 0; k < KDIM; k++) acc += rbf[k] * __ldg(w + k * CDIM);
                fn[m] = acc;
            }

            size_t bj = (size_t)j * CDIM + c;
            float s0 = __ldg(t0 + bj);
            float va[3];
            va[0] = __ldg(t1 + bj * 3 + 0);
            va[1] = __ldg(t1 + bj * 3 + 1);
            va[2] = __ldg(t1 + bj * 3 + 2);
            float M[9];
#pragma unroll
            for (int m9 = 0; m9 < 9; m9++) M[m9] = __ldg(t2 + bj * 9 + m9);

            float u[3] = {ux, uy, uz};
            float d1 = va[0] * ux + va[1] * uy + va[2] * uz;
            float w3[3];
#pragma unroll
            for (int a = 0; a < 3; a++)
                w3[a] = M[a * 3 + 0] * ux + M[a * 3 + 1] * uy + M[a * 3 + 2] * uz;
            float q2 = w3[0] * ux + w3[1] * uy + w3[2] * uz;

            const float sc = 1.0f / NORMF;
            float o0 = (fn[0] * s0 + fn[4] * d1 + fn[9] * q2) * sc;
            float c1 = fn[1] * s0 + fn[6] * d1;
            float o1[3];
#pragma unroll
            for (int p = 0; p < 3; p++)
                o1[p] = (c1 * u[p] + fn[3] * va[p] + fn[8] * w3[p]) * sc;
            float o2[9];
#pragma unroll
            for (int a = 0; a < 3; a++) {
                float ga = fn[2] * s0 * u[a] + fn[5] * va[a] + fn[10] * w3[a];
#pragma unroll
                for (int b = 0; b < 3; b++)
                    o2[a * 3 + b] = (ga * u[b] + fn[7] * M[a * 3 + b]) * sc;
            }

            size_t bi = (size_t)i * CDIM + c;
            atomicAdd(&g_scr[bi], o0);
#pragma unroll
            for (int p = 0; p < 3; p++) atomicAdd(&g_scr[(size_t)(1 + p) * NC + bi], o1[p]);
#pragma unroll
            for (int m9 = 0; m9 < 9; m9++) atomicAdd(&g_scr[(size_t)(4 + m9) * NC + bi], o2[m9]);
        }
        __syncthreads();
    }
}

__device__ __forceinline__ float sigf(float x) { return 1.0f / (1.0f + __expf(-x)); }

// Persistent, weight-stationary. TATOMS=16 atoms/tile; thread = (atom, 4 out channels).
// Inner loop unrolled x4 over cc: 13 agg LDS.128 + 12 weight LDS.128 per 4 cc
// feed 208 FMAs -> 6.25 LDS/cc (was 16), L1-wavefront pressure cut ~4x.
__global__ void __launch_bounds__(256, 2)
k_si(const float* __restrict__ t0, const float* __restrict__ t1,
     const float* __restrict__ t2,
     const float* __restrict__ w0, const float* __restrict__ b0,
     const float* __restrict__ w1, const float* __restrict__ w2,
     const float* __restrict__ actw, float* __restrict__ out) {
    extern __shared__ float ws[];                       // [3][64][64] = 48KB dynamic
    __shared__ float aggS[TATOMS * ASTRIDE];            // 53504 B
    __shared__ float b0s[CDIM], aws[3][CDIM];

    const int tid = threadIdx.x;
    for (int idx = tid; idx < 3 * CDIM * CDIM; idx += 256) {
        int which = idx >> 12;
        int r = idx & 4095;
        const float* src = (which == 0) ? w0 : ((which == 1) ? w1 : w2);
        ws[idx] = src[r];
    }
    if (tid < CDIM) {
        b0s[tid] = b0[tid];
        aws[0][tid] = actw[tid];
        aws[1][tid] = actw[CDIM + tid];
        aws[2][tid] = actw[2 * CDIM + tid];
    }

    const int a = tid >> 4;            // atom within tile
    const int o4 = (tid & 15) * 4;     // first of 4 output channels
    const int sa = tid >> 6;           // staging: 4 atoms per pass
    const int sc_ = tid & 63;          // staging: channel
    const float* W0 = ws;
    const float* W1 = ws + CDIM * CDIM;
    const float* W2 = ws + 2 * CDIM * CDIM;
    float* out1 = out + (size_t)NATOMS * CDIM;
    float* out2 = out + (size_t)NATOMS * CDIM * 4;

    for (int tile = blockIdx.x; tile < NATOMS / TATOMS; tile += gridDim.x) {
        const int nbase = tile * TATOMS;
        // ---- stage: agg = t (residual start) + scratch (touched atoms only) ----
#pragma unroll
        for (int pass = 0; pass < 4; pass++) {
            int aa = sa + pass * 4;
            int n_a = nbase + aa;
            size_t gb = (size_t)n_a * CDIM + sc_;
            float v[13];
            v[0] = t0[gb];
#pragma unroll
            for (int p = 0; p < 3; p++) v[1 + p] = t1[gb * 3 + p];
#pragma unroll
            for (int m = 0; m < 9; m++) v[4 + m] = t2[gb * 9 + m];
            if (g_flag[n_a]) {
#pragma unroll
                for (int s = 0; s < 13; s++) v[s] += g_scr[(size_t)s * NC + gb];
            }
#pragma unroll
            for (int s = 0; s < 13; s++) aggS[aa * ASTRIDE + s * 64 + sc_] = v[s];
        }
        __syncthreads();

        // ---- compute: 52 accumulators, cc unrolled x4 with float4 loads ----
        float y0[4], y1[3][4], y2[9][4];
#pragma unroll
        for (int q = 0; q < 4; q++) y0[q] = b0s[o4 + q];
#pragma unroll
        for (int s = 0; s < 3; s++)
#pragma unroll
            for (int q = 0; q < 4; q++) y1[s][q] = 0.f;
#pragma unroll
        for (int s = 0; s < 9; s++)
#pragma unroll
            for (int q = 0; q < 4; q++) y2[s][q] = 0.f;

        const float* ag = &aggS[a * ASTRIDE];
        for (int cc = 0; cc < CDIM; cc += 4) {
            float4 wv0[4], wv1[4], wv2[4];
#pragma unroll
            for (int u = 0; u < 4; u++) {
                wv0[u] = *reinterpret_cast<const float4*>(&W0[(cc + u) * CDIM + o4]);
                wv1[u] = *reinterpret_cast<const float4*>(&W1[(cc + u) * CDIM + o4]);
                wv2[u] = *reinterpret_cast<const float4*>(&W2[(cc + u) * CDIM + o4]);
            }
            {
                float4 av = *reinterpret_cast<const float4*>(&ag[cc]);
                y0[0] += av.x * wv0[0].x + av.y * wv0[1].x + av.z * wv0[2].x + av.w * wv0[3].x;
                y0[1] += av.x * wv0[0].y + av.y * wv0[1].y + av.z * wv0[2].y + av.w * wv0[3].y;
                y0[2] += av.x * wv0[0].z + av.y * wv0[1].z + av.z * wv0[2].z + av.w * wv0[3].z;
                y0[3] += av.x * wv0[0].w + av.y * wv0[1].w + av.z * wv0[2].w + av.w * wv0[3].w;
            }
#pragma unroll
            for (int s = 0; s < 3; s++) {
                float4 av = *reinterpret_cast<const float4*>(&ag[(1 + s) * 64 + cc]);
                y1[s][0] += av.x * wv1[0].x + av.y * wv1[1].x + av.z * wv1[2].x + av.w * wv1[3].x;
                y1[s][1] += av.x * wv1[0].y + av.y * wv1[1].y + av.z * wv1[2].y + av.w * wv1[3].y;
                y1[s][2] += av.x * wv1[0].z + av.y * wv1[1].z + av.z * wv1[2].z + av.w * wv1[3].z;
                y1[s][3] += av.x * wv1[0].w + av.y * wv1[1].w + av.z * wv1[2].w + av.w * wv1[3].w;
            }
#pragma unroll
            for (int s = 0; s < 9; s++) {
                float4 av = *reinterpret_cast<const float4*>(&ag[(4 + s) * 64 + cc]);
                y2[s][0] += av.x * wv2[0].x + av.y * wv2[1].x + av.z * wv2[2].x + av.w * wv2[3].x;
                y2[s][1] += av.x * wv2[0].y + av.y * wv2[1].y + av.z * wv2[2].y + av.w * wv2[3].y;
                y2[s][2] += av.x * wv2[0].z + av.y * wv2[1].z + av.z * wv2[2].z + av.w * wv2[3].z;
                y2[s][3] += av.x * wv2[0].w + av.y * wv2[1].w + av.z * wv2[2].w + av.w * wv2[3].w;
            }
        }

        // ---- activations + residual; contiguous float4 stores ----
        const int n = nbase + a;
        float r0v[4], r1v[12], r2v[36];
#pragma unroll
        for (int q = 0; q < 4; q++) {
            int o = o4 + q;
            float z0 = y0[q] * sigf(aws[0][o] * y0[q]);
            float n1 = y1[0][q] * y1[0][q] + y1[1][q] * y1[1][q] + y1[2][q] * y1[2][q];
            float g1 = sigf(aws[1][o] * sqrtf(n1 + EPSF));
            float n2 = 0.f;
#pragma unroll
            for (int s = 0; s < 9; s++) n2 += y2[s][q] * y2[s][q];
            float g2 = sigf(aws[2][o] * sqrtf(n2 + EPSF));
            r0v[q] = z0 + ag[o];
#pragma unroll
            for (int s = 0; s < 3; s++) r1v[q * 3 + s] = y1[s][q] * g1 + ag[(1 + s) * 64 + o];
#pragma unroll
            for (int s = 0; s < 9; s++) r2v[q * 9 + s] = y2[s][q] * g2 + ag[(4 + s) * 64 + o];
        }
        {
            size_t b = (size_t)n * CDIM + o4;
            *reinterpret_cast<float4*>(&out[b]) = make_float4(r0v[0], r0v[1], r0v[2], r0v[3]);
            float* p1 = out1 + b * 3;
#pragma unroll
            for (int v = 0; v < 3; v++)
                *reinterpret_cast<float4*>(&p1[v * 4]) =
                    make_float4(r1v[v * 4 + 0], r1v[v * 4 + 1], r1v[v * 4 + 2], r1v[v * 4 + 3]);
            float* p2 = out2 + b * 9;
#pragma unroll
            for (int v = 0; v < 9; v++)
                *reinterpret_cast<float4*>(&p2[v * 4]) =
                    make_float4(r2v[v * 4 + 0], r2v[v * 4 + 1], r2v[v * 4 + 2], r2v[v * 4 + 3]);
        }
        __syncthreads();   // aggS reused next tile
    }
}

extern "C" void kernel_launch(void* const* d_in, const int* in_sizes, int n_in,
                              void* d_out, int out_size) {
    const float* t0    = (const float*)d_in[0];
    const float* t1    = (const float*)d_in[1];
    const float* t2    = (const float*)d_in[2];
    const float* coord = (const float*)d_in[3];
    const int*   eidx  = (const int*)d_in[4];
    const float* rbf_w = (const float*)d_in[5];
    const float* w0    = (const float*)d_in[6];
    const float* b0    = (const float*)d_in[7];
    const float* w1    = (const float*)d_in[8];
    const float* w2    = (const float*)d_in[9];
    const float* aw    = (const float*)d_in[10];
    float* out = (float*)d_out;

    cudaFuncSetAttribute(k_si, cudaFuncAttributeMaxDynamicSharedMemorySize,
                         3 * CDIM * CDIM * (int)sizeof(float));

    k_reset<<<(NATOMS + 255) / 256, 256>>>();
    k_compact<<<(NEDGES + 255) / 256, 256>>>(eidx, coord);
    k_zero_touched<<<2048, 64>>>();
    k_edge<<<888, 256>>>(eidx, coord, t0, t1, t2, rbf_w);
    k_si<<<296, 256, 3 * CDIM * CDIM * sizeof(float)>>>(t0, t1, t2, w0, b0, w1, w2, aw, out);
}